// round 10
// baseline (speedup 1.0000x reference)
#include <cuda_runtime.h>
#include <cstdint>

// Problem constants
#define BATCH    16
#define HW       (1024 * 1024)
#define HW4      (HW / 4)
#define GRIDX    37            // 37*16 = 592 = 148 SMs * 4 CTAs -> one exact wave
#define NT       256
#define NQ       7             // f(alpha*g), lg, omp, tomp, t, bin, bint
#define SMOOTH   1e-6f
#define NBLOCKS  (GRIDX * BATCH)

#define NSLOT    4
#define NCHUNK   (HW4 / NT)    // 1024 chunks per image, 256 float4 each

__device__ float        g_part[BATCH * GRIDX * 8];
__device__ unsigned int g_count;          // zero-init; reset in epilogue
__device__ unsigned int g_next[BATCH];    // zero-init; reset in epilogue

typedef unsigned long long ull;

// ---------- f32x2 packed helpers ----------
__device__ __forceinline__ ull pk2(float lo, float hi) {
    ull r; asm("mov.b64 %0, {%1, %2};" : "=l"(r) : "f"(lo), "f"(hi)); return r;
}
__device__ __forceinline__ void upk2(ull v, float& lo, float& hi) {
    asm("mov.b64 {%0, %1}, %2;" : "=f"(lo), "=f"(hi) : "l"(v));
}
__device__ __forceinline__ ull mul2(ull a, ull b) {
    ull r; asm("mul.rn.f32x2 %0, %1, %2;" : "=l"(r) : "l"(a), "l"(b)); return r;
}
__device__ __forceinline__ ull add2(ull a, ull b) {
    ull r; asm("add.rn.f32x2 %0, %1, %2;" : "=l"(r) : "l"(a), "l"(b)); return r;
}
__device__ __forceinline__ ull fma2(ull a, ull b, ull c) {
    ull r; asm("fma.rn.f32x2 %0, %1, %2, %3;" : "=l"(r) : "l"(a), "l"(b), "l"(c)); return r;
}
__device__ __forceinline__ float tanha(float x) {
    float r; asm("tanh.approx.f32 %0, %1;" : "=f"(r) : "f"(x)); return r;
}
__device__ __forceinline__ float lg2a(float x) {
    float r; asm("lg2.approx.f32 %0, %1;" : "=f"(r) : "f"(x)); return r;
}
__device__ __forceinline__ float setgt0(float x) {
    float r; asm("set.gt.f32.f32 %0, %1, 0f00000000;" : "=f"(r) : "f"(x)); return r;
}

// ---------- cp.async helpers ----------
__device__ __forceinline__ uint32_t smem_u32(const void* p) {
    uint32_t a;
    asm("{ .reg .u64 t; cvta.to.shared.u64 t, %1; cvt.u32.u64 %0, t; }" : "=r"(a) : "l"(p));
    return a;
}
__device__ __forceinline__ void cp16(uint32_t dst, const void* src) {
    asm volatile("cp.async.cg.shared.global [%0], [%1], 16;"
                 :: "r"(dst), "l"(src) : "memory");
}
__device__ __forceinline__ void cp_commit() {
    asm volatile("cp.async.commit_group;" ::: "memory");
}
__device__ __forceinline__ void cp_wait2() {
    asm volatile("cp.async.wait_group 2;" ::: "memory");
}
__device__ __forceinline__ void cp_wait0() {
    asm volatile("cp.async.wait_group 0;" ::: "memory");
}

struct Accs { ull f, lg, omp, tomp, t, bin, bint; };

// Per-pair math, t in {0,1}:
//   h = tanh((t-0.5)x) ; p_t = 0.5+0.5h ; ce = -ln2*lg2(p_t) ; omp = 0.5-0.5h
//   focal elem = (0.75-0.5t)*lg2(p_t)*omp^2   (-ln2 folded in epilogue)
//   Sp = omp + t - 2*tomp ; Spt = t - tomp     (recovered in epilogue)
__device__ __forceinline__ void group(Accs& A, float x0, float x1, float t0, float t1,
                                      ull HALF2, ull MHALF2, ull K75) {
    ull x2 = pk2(x0, x1);
    ull t2 = pk2(t0, t1);
    ull c2 = add2(t2, MHALF2);           // t - 0.5
    ull z2 = mul2(x2, c2);
    float z0, z1; upk2(z2, z0, z1);
    float h0 = tanha(z0), h1 = tanha(z1);
    ull h2 = pk2(h0, h1);
    ull pt2 = fma2(h2, HALF2, HALF2);
    float q0, q1; upk2(pt2, q0, q1);
    float l0 = lg2a(q0), l1 = lg2a(q1);
    ull l2 = pk2(l0, l1);
    ull omp2 = fma2(h2, MHALF2, HALF2);
    ull o2   = mul2(omp2, omp2);
    ull g2   = mul2(l2, o2);
    ull a2   = fma2(t2, MHALF2, K75);
    A.f    = fma2(a2, g2, A.f);
    A.lg   = add2(A.lg, l2);
    A.omp  = add2(A.omp, omp2);
    A.tomp = fma2(t2, omp2, A.tomp);
    A.t    = add2(A.t, t2);
    ull bin2 = pk2(setgt0(x0), setgt0(x1));
    A.bin  = add2(A.bin, bin2);
    A.bint = fma2(t2, bin2, A.bint);
}

__device__ __forceinline__ float warp_sum(float v) {
    #pragma unroll
    for (int off = 16; off > 0; off >>= 1)
        v += __shfl_xor_sync(0xFFFFFFFFu, v, off);
    return v;
}

__global__ __launch_bounds__(NT, 4)
void loss_fused_kernel(const float4* __restrict__ pred,
                       const float4* __restrict__ gt,
                       const float*  __restrict__ pred_iou,
                       float*        __restrict__ out) {
    __shared__ float4 st_p[NSLOT][NT];      // 16 KB
    __shared__ float4 st_g[NSLOT][NT];      // 16 KB
    __shared__ int    s_chunk[8];           // chunk-id ring, indexed by j&7

    const int tid = threadIdx.x;
    const int img = blockIdx.y;

    const float4* pimg = pred + (size_t)img * HW4;
    const float4* gimg = gt   + (size_t)img * HW4;

    const uint32_t spb = smem_u32(&st_p[0][tid]);   // + slot*(NT*16)
    const uint32_t sgb = smem_u32(&st_g[0][tid]);

    // -------- prologue: steal chunk ids for j=0..3 and stage j=0..2 --------
    if (tid == 0) {
        #pragma unroll
        for (int k = 0; k < 4; k++)
            s_chunk[k] = (int)atomicAdd(&g_next[img], 1u);
    }
    __syncthreads();
    #pragma unroll
    for (int k = 0; k < NSLOT - 1; k++) {
        int c = s_chunk[k];                 // < 148, always valid
        cp16(spb + (uint32_t)k * (NT * 16), pimg + (size_t)c * NT + tid);
        cp16(sgb + (uint32_t)k * (NT * 16), gimg + (size_t)c * NT + tid);
        cp_commit();
    }

    const ull HALF2  = pk2(0.5f, 0.5f);
    const ull MHALF2 = pk2(-0.5f, -0.5f);
    const ull K75    = pk2(0.75f, 0.75f);

    Accs A;
    A.f = A.lg = A.omp = A.tomp = A.t = A.bin = A.bint = pk2(0.0f, 0.0f);

    // -------- stealing main loop --------
    for (int j = 0; ; j++) {
        __syncthreads();                    // publishes s_chunk[(j+3)&7] from iter j-1
        const int c = s_chunk[j & 7];
        if (c >= NCHUNK) break;             // uniform across CTA

        const int c3 = s_chunk[(j + 3) & 7];
        if (tid == 0)                       // steal id for iteration j+4
            s_chunk[(j + 4) & 7] = (int)atomicAdd(&g_next[img], 1u);

        cp_wait2();                         // slot j&3 data ready
        const int slot = j & (NSLOT - 1);
        float4 p4 = st_p[slot][tid];
        float4 g4 = st_g[slot][tid];

        if (c3 < NCHUNK) {                  // prefetch chunk c3 into slot (j+3)&3
            const uint32_t soff = (uint32_t)((j + 3) & (NSLOT - 1)) * (NT * 16);
            cp16(spb + soff, pimg + (size_t)c3 * NT + tid);
            cp16(sgb + soff, gimg + (size_t)c3 * NT + tid);
        }
        cp_commit();

        group(A, p4.x, p4.y, g4.x, g4.y, HALF2, MHALF2, K75);
        group(A, p4.z, p4.w, g4.z, g4.w, HALF2, MHALF2, K75);
    }
    cp_wait0();                             // drain stragglers before reusing nothing

    // collapse packed halves
    float vals[NQ];
    {
        float lo, hi;
        upk2(A.f,    lo, hi); vals[0] = lo + hi;
        upk2(A.lg,   lo, hi); vals[1] = lo + hi;
        upk2(A.omp,  lo, hi); vals[2] = lo + hi;
        upk2(A.tomp, lo, hi); vals[3] = lo + hi;
        upk2(A.t,    lo, hi); vals[4] = lo + hi;
        upk2(A.bin,  lo, hi); vals[5] = lo + hi;
        upk2(A.bint, lo, hi); vals[6] = lo + hi;
    }

    // -------- block reduction --------
    #pragma unroll
    for (int q = 0; q < NQ; q++) vals[q] = warp_sum(vals[q]);

    __shared__ float sm[NT / 32][NQ];
    const int lane = tid & 31;
    const int warp = tid >> 5;
    if (lane == 0) {
        #pragma unroll
        for (int q = 0; q < NQ; q++) sm[warp][q] = vals[q];
    }
    __syncthreads();

    __shared__ bool is_last;
    if (warp == 0) {
        #pragma unroll
        for (int q = 0; q < NQ; q++) {
            float v = (lane < NT / 32) ? sm[lane][q] : 0.0f;
            v = warp_sum(v);
            if (lane == 0) vals[q] = v;
        }
        if (lane == 0) {
            float* dst = g_part + ((size_t)img * GRIDX + blockIdx.x) * 8;
            #pragma unroll
            for (int q = 0; q < NQ; q++) dst[q] = vals[q];
            __threadfence();
            unsigned int v = atomicAdd(&g_count, 1u);
            is_last = (v == (unsigned int)(NBLOCKS - 1));
        }
    }
    __syncthreads();
    if (!is_last) return;

    // -------- epilogue: last block reduces 592 partials --------
    __shared__ float agg[BATCH][4];
    for (int b = warp; b < BATCH; b += NT / 32) {
        float s[NQ] = {0.f, 0.f, 0.f, 0.f, 0.f, 0.f, 0.f};
        for (int j = lane; j < GRIDX; j += 32) {
            const float* q = g_part + ((size_t)b * GRIDX + j) * 8;
            #pragma unroll
            for (int k = 0; k < NQ; k++) s[k] += q[k];
        }
        #pragma unroll
        for (int k = 0; k < NQ; k++) s[k] = warp_sum(s[k]);
        if (lane == 0) {
            // s: 0=f 1=lg 2=omp 3=tomp 4=t 5=bin 6=bint
            float Sp  = s[2] + s[4] - 2.0f * s[3];   // sum p
            float Spt = s[4] - s[3];                 // sum p*t
            float dice_term = (2.0f * Spt + SMOOTH) / (Sp + s[4] + SMOOTH);
            float inter  = s[6];
            float uni    = s[5] + s[4] - s[6];
            float actual = (inter + SMOOTH) / (uni + SMOOTH);
            float d = pred_iou[b] - actual;
            agg[b][0] = s[0];
            agg[b][1] = s[1];
            agg[b][2] = dice_term;
            agg[b][3] = d * d;
        }
    }
    __syncthreads();

    if (tid == 0) {
        float fsum = 0.f, csum = 0.f, dsum = 0.f, isum = 0.f;
        #pragma unroll
        for (int b = 0; b < BATCH; b++) {
            fsum += agg[b][0];
            csum += agg[b][1];
            dsum += agg[b][2];
            isum += agg[b][3];
        }
        const float NLN2 = -0.6931471805599453f;
        const float invN = 1.0f / (float)((long long)BATCH * HW);
        float focal    = NLN2 * fsum * invN;
        float dice     = 1.0f - dsum / (float)BATCH;
        float boundary = NLN2 * csum * invN;   // mean(ce) = 0.5*(2*mean(ce))
        float iou_loss = 0.1f * (isum / (float)BATCH);
        out[0] = focal + dice + boundary + iou_loss;
        g_count = 0;   // reset for next graph replay
    }
    // reset steal counters for next graph replay
    if (tid < BATCH) g_next[tid] = 0u;
}

extern "C" void kernel_launch(void* const* d_in, const int* in_sizes, int n_in,
                              void* d_out, int out_size) {
    const float4* pred = (const float4*)d_in[0];
    const float4* gt   = (const float4*)d_in[1];
    const float*  piou = (const float*)d_in[2];
    float* out = (float*)d_out;

    dim3 grid(GRIDX, BATCH);
    loss_fused_kernel<<<grid, NT>>>(pred, gt, piou, out);
}

// round 11
// speedup vs baseline: 1.1754x; 1.1754x over previous
#include <cuda_runtime.h>
#include <cstdint>

// Problem constants
#define BATCH    16
#define HW       (1024 * 1024)
#define HW4      (HW / 4)
#define GRIDX    37            // 37*16 = 592 = 148 SMs * 4 CTAs -> one exact wave
#define NT       256
#define NQ       8             // g, tg, lg, omp, tomp, t, bin, bint
#define SMOOTH   1e-6f
#define NBLOCKS  (GRIDX * BATCH)

#define NSLOT    4
#define STRIDE   (GRIDX * NT)              // 9472 float4s
// 28 positions per thread: even k (0..26) via cp.async (always in-bounds),
// odd k (1..27) via LDG (k=27 partial, guarded).
#define NJ       14

__device__ float        g_part[BATCH * GRIDX * NQ];
__device__ unsigned int g_count;   // zero-init; self-resets each launch

// ---------- scalar MUFU helpers ----------
__device__ __forceinline__ float tanha(float x) {
    float r; asm("tanh.approx.f32 %0, %1;" : "=f"(r) : "f"(x)); return r;
}
__device__ __forceinline__ float lg2a(float x) {
    float r; asm("lg2.approx.f32 %0, %1;" : "=f"(r) : "f"(x)); return r;
}
__device__ __forceinline__ float setgt0(float x) {
    float r; asm("set.gt.f32.f32 %0, %1, 0f00000000;" : "=f"(r) : "f"(x)); return r;
}

// ---------- cp.async helpers ----------
__device__ __forceinline__ uint32_t smem_u32(const void* p) {
    uint32_t a;
    asm("{ .reg .u64 t; cvta.to.shared.u64 t, %1; cvt.u32.u64 %0, t; }" : "=r"(a) : "l"(p));
    return a;
}
__device__ __forceinline__ void cp16(uint32_t dst, const void* src) {
    asm volatile("cp.async.cg.shared.global [%0], [%1], 16;"
                 :: "r"(dst), "l"(src) : "memory");
}
__device__ __forceinline__ void cp_commit() {
    asm volatile("cp.async.commit_group;" ::: "memory");
}
__device__ __forceinline__ void cp_wait2() {
    asm volatile("cp.async.wait_group 2;" ::: "memory");
}

struct Accs { float g, tg, lg, om, to, t, bn, bt; };

// Per-element, t in {0,1}:
//   h = tanh((t-0.5)x) ; p_t = 0.5+0.5h ; l = lg2(p_t)  (ce = -ln2*l)
//   omp = 1-p_t = 0.5-0.5h ; focal elem = (0.75-0.5t)*(-ln2)*l*omp^2
//   Sp = om + t - 2*to ; Spt = t - to  (recovered in epilogue)
__device__ __forceinline__ void elem(Accs& A, float x, float t) {
    float z   = (t - 0.5f) * x;
    float h   = tanha(z);                  // MUFU
    float pt  = fmaf(h, 0.5f, 0.5f);
    float l   = lg2a(pt);                  // MUFU
    float omp = fmaf(h, -0.5f, 0.5f);
    float gg  = l * omp * omp;
    A.g  += gg;
    A.tg  = fmaf(t, gg, A.tg);
    A.lg += l;
    A.om += omp;
    A.to  = fmaf(t, omp, A.to);
    A.t  += t;
    float b = setgt0(x);
    A.bn += b;
    A.bt  = fmaf(t, b, A.bt);
}

__device__ __forceinline__ float warp_sum(float v) {
    #pragma unroll
    for (int off = 16; off > 0; off >>= 1)
        v += __shfl_xor_sync(0xFFFFFFFFu, v, off);
    return v;
}

__global__ __launch_bounds__(NT, 4)
void loss_fused_kernel(const float4* __restrict__ pred,
                       const float4* __restrict__ gt,
                       const float*  __restrict__ pred_iou,
                       float*        __restrict__ out) {
    __shared__ float4 st_p[NSLOT][NT];   // 16 KB  (even positions, pred)
    __shared__ float4 st_g[NSLOT][NT];   // 16 KB  (even positions, gt)

    const int tid = threadIdx.x;
    const int img = blockIdx.y;

    const float4* pimg = pred + (size_t)img * HW4;
    const float4* gimg = gt   + (size_t)img * HW4;

    const uint32_t spb = smem_u32(&st_p[0][tid]);
    const uint32_t sgb = smem_u32(&st_g[0][tid]);

    const int  base    = blockIdx.x * NT + tid;
    const bool valid27 = (base + 27 * STRIDE) < HW4;

    // -------- cp.async prologue: slots 0..2 <- even positions 0,2,4 --------
    #pragma unroll
    for (int k = 0; k < NSLOT - 1; k++) {
        cp16(spb + (uint32_t)k * (NT * 16), pimg + base + (2 * k) * STRIDE);
        cp16(sgb + (uint32_t)k * (NT * 16), gimg + base + (2 * k) * STRIDE);
        cp_commit();
    }

    // -------- LDG prologue: odd position 1 --------
    float4 cp_ = __ldg(pimg + base + STRIDE);
    float4 cg_ = __ldg(gimg + base + STRIDE);

    Accs A = {0.f, 0.f, 0.f, 0.f, 0.f, 0.f, 0.f, 0.f};

    #pragma unroll 2
    for (int j = 0; j < NJ; j++) {
        // issue LDG for odd position 2j+3 (guard k=27 OOB for img boundary)
        float4 np = cp_, ng = cg_;
        if (j < NJ - 1) {
            const int kodd = 2 * j + 3;
            if (kodd < 27 || valid27) {
                np = __ldg(pimg + base + kodd * STRIDE);
                ng = __ldg(gimg + base + kodd * STRIDE);
            }
        }

        // smem path: even position 2j (always in-bounds)
        cp_wait2();
        const int slot = j & (NSLOT - 1);
        float4 sp4 = st_p[slot][tid];
        float4 sg4 = st_g[slot][tid];

        // prefetch even position 2j+6 into slot (j+3)&3
        if (j <= 10) {
            const uint32_t soff = (uint32_t)((j + 3) & (NSLOT - 1)) * (NT * 16);
            cp16(spb + soff, pimg + base + (2 * j + 6) * STRIDE);
            cp16(sgb + soff, gimg + base + (2 * j + 6) * STRIDE);
        }
        cp_commit();

        elem(A, sp4.x, sg4.x); elem(A, sp4.y, sg4.y);
        elem(A, sp4.z, sg4.z); elem(A, sp4.w, sg4.w);

        // LDG path: odd position 2j+1 (j=13 -> k=27, partial)
        if (j < NJ - 1 || valid27) {
            elem(A, cp_.x, cg_.x); elem(A, cp_.y, cg_.y);
            elem(A, cp_.z, cg_.z); elem(A, cp_.w, cg_.w);
        }
        cp_ = np; cg_ = ng;
    }

    // -------- block reduction --------
    float vals[NQ] = {A.g, A.tg, A.lg, A.om, A.to, A.t, A.bn, A.bt};
    #pragma unroll
    for (int q = 0; q < NQ; q++) vals[q] = warp_sum(vals[q]);

    __shared__ float sm[NT / 32][NQ];
    const int lane = tid & 31;
    const int warp = tid >> 5;
    if (lane == 0) {
        #pragma unroll
        for (int q = 0; q < NQ; q++) sm[warp][q] = vals[q];
    }
    __syncthreads();

    __shared__ bool is_last;
    if (warp == 0) {
        #pragma unroll
        for (int q = 0; q < NQ; q++) {
            float v = (lane < NT / 32) ? sm[lane][q] : 0.0f;
            v = warp_sum(v);
            if (lane == 0) vals[q] = v;
        }
        if (lane == 0) {
            float* dst = g_part + ((size_t)img * GRIDX + blockIdx.x) * NQ;
            #pragma unroll
            for (int q = 0; q < NQ; q++) dst[q] = vals[q];
            __threadfence();
            unsigned int v = atomicAdd(&g_count, 1u);
            is_last = (v == (unsigned int)(NBLOCKS - 1));
        }
    }
    __syncthreads();
    if (!is_last) return;

    // -------- epilogue: last block reduces 592 partials --------
    __shared__ float agg[BATCH][4];
    for (int b = warp; b < BATCH; b += NT / 32) {
        float s[NQ] = {0.f, 0.f, 0.f, 0.f, 0.f, 0.f, 0.f, 0.f};
        for (int j = lane; j < GRIDX; j += 32) {
            const float* q = g_part + ((size_t)b * GRIDX + j) * NQ;
            #pragma unroll
            for (int k = 0; k < NQ; k++) s[k] += q[k];
        }
        #pragma unroll
        for (int k = 0; k < NQ; k++) s[k] = warp_sum(s[k]);
        if (lane == 0) {
            // s: 0=g 1=tg 2=lg 3=om 4=to 5=t 6=bn 7=bt
            float Sp  = s[3] + s[5] - 2.0f * s[4];   // sum p
            float Spt = s[5] - s[4];                 // sum p*t
            float dice_term = (2.0f * Spt + SMOOTH) / (Sp + s[5] + SMOOTH);
            float inter  = s[7];
            float uni    = s[6] + s[5] - s[7];
            float actual = (inter + SMOOTH) / (uni + SMOOTH);
            float d = pred_iou[b] - actual;
            agg[b][0] = 0.75f * s[0] - 0.5f * s[1];  // x (-ln2) later
            agg[b][1] = s[2];                        // x (-ln2) later -> sum ce
            agg[b][2] = dice_term;
            agg[b][3] = d * d;
        }
    }
    __syncthreads();

    if (tid == 0) {
        float fsum = 0.f, csum = 0.f, dsum = 0.f, isum = 0.f;
        #pragma unroll
        for (int b = 0; b < BATCH; b++) {
            fsum += agg[b][0];
            csum += agg[b][1];
            dsum += agg[b][2];
            isum += agg[b][3];
        }
        const float NLN2 = -0.6931471805599453f;
        const float invN = 1.0f / (float)((long long)BATCH * HW);
        float focal    = NLN2 * fsum * invN;
        float dice     = 1.0f - dsum / (float)BATCH;
        float boundary = NLN2 * csum * invN;   // mean(ce) = 0.5*(2*mean(ce))
        float iou_loss = 0.1f * (isum / (float)BATCH);
        out[0] = focal + dice + boundary + iou_loss;
        g_count = 0;   // reset for next graph replay
    }
}

extern "C" void kernel_launch(void* const* d_in, const int* in_sizes, int n_in,
                              void* d_out, int out_size) {
    const float4* pred = (const float4*)d_in[0];
    const float4* gt   = (const float4*)d_in[1];
    const float*  piou = (const float*)d_in[2];
    float* out = (float*)d_out;

    dim3 grid(GRIDX, BATCH);
    loss_fused_kernel<<<grid, NT>>>(pred, gt, piou, out);
}

// round 13
// speedup vs baseline: 1.1767x; 1.0011x over previous
#include <cuda_runtime.h>
#include <cstdint>

// Problem constants
#define BATCH    16
#define HW       (1024 * 1024)
#define HW4      (HW / 4)
#define GRIDX    37            // 37*16 = 592 = 148 SMs * 4 CTAs -> one exact wave
#define NT       256
#define NQ       7             // f(alpha*g), lg, omp, tomp, t, bin, bint
#define SMOOTH   1e-6f
#define NBLOCKS  (GRIDX * BATCH)

#define NSLOT    4
#define CHUNK    (28 * NT)     // 7168 float4: contiguous block per CTA
// CTAs 0..35: 28 stages. CTA 36: (HW4 - 36*7168)/256 = 16 stages. All stage-
// granular (no partial stages).

__device__ float        g_part[BATCH * GRIDX * 8];
__device__ unsigned int g_count;   // zero-init; self-resets each launch

typedef unsigned long long ull;

// ---------- f32x2 packed helpers ----------
__device__ __forceinline__ ull pk2(float lo, float hi) {
    ull r; asm("mov.b64 %0, {%1, %2};" : "=l"(r) : "f"(lo), "f"(hi)); return r;
}
__device__ __forceinline__ void upk2(ull v, float& lo, float& hi) {
    asm("mov.b64 {%0, %1}, %2;" : "=f"(lo), "=f"(hi) : "l"(v));
}
__device__ __forceinline__ ull mul2(ull a, ull b) {
    ull r; asm("mul.rn.f32x2 %0, %1, %2;" : "=l"(r) : "l"(a), "l"(b)); return r;
}
__device__ __forceinline__ ull add2(ull a, ull b) {
    ull r; asm("add.rn.f32x2 %0, %1, %2;" : "=l"(r) : "l"(a), "l"(b)); return r;
}
__device__ __forceinline__ ull fma2(ull a, ull b, ull c) {
    ull r; asm("fma.rn.f32x2 %0, %1, %2, %3;" : "=l"(r) : "l"(a), "l"(b), "l"(c)); return r;
}
__device__ __forceinline__ float tanha(float x) {
    float r; asm("tanh.approx.f32 %0, %1;" : "=f"(r) : "f"(x)); return r;
}
__device__ __forceinline__ float lg2a(float x) {
    float r; asm("lg2.approx.f32 %0, %1;" : "=f"(r) : "f"(x)); return r;
}
__device__ __forceinline__ float setgt0(float x) {
    float r; asm("set.gt.f32.f32 %0, %1, 0f00000000;" : "=f"(r) : "f"(x)); return r;
}

// ---------- cp.async helpers ----------
__device__ __forceinline__ uint32_t smem_u32(const void* p) {
    uint32_t a;
    asm("{ .reg .u64 t; cvta.to.shared.u64 t, %1; cvt.u32.u64 %0, t; }" : "=r"(a) : "l"(p));
    return a;
}
__device__ __forceinline__ void cp16(uint32_t dst, const void* src) {
    asm volatile("cp.async.cg.shared.global [%0], [%1], 16;"
                 :: "r"(dst), "l"(src) : "memory");
}
__device__ __forceinline__ void cp_commit() {
    asm volatile("cp.async.commit_group;" ::: "memory");
}
__device__ __forceinline__ void cp_wait2() {
    asm volatile("cp.async.wait_group 2;" ::: "memory");
}

struct Accs { ull f, lg, omp, tomp, t, bin, bint; };

// Per-pair math, t in {0,1}:
//   h = tanh((t-0.5)x) ; p_t = 0.5+0.5h ; ce = -ln2*lg2(p_t) ; omp = 0.5-0.5h
//   focal elem = (0.75-0.5t)*lg2(p_t)*omp^2    (-ln2 folded in epilogue)
//   Sp = omp + t - 2*tomp ; Spt = t - tomp      (recovered in epilogue)
__device__ __forceinline__ void group(Accs& A, float x0, float x1, float t0, float t1,
                                      ull HALF2, ull MHALF2, ull K75) {
    ull x2 = pk2(x0, x1);
    ull t2 = pk2(t0, t1);
    ull c2 = add2(t2, MHALF2);           // t - 0.5
    ull z2 = mul2(x2, c2);
    float z0, z1; upk2(z2, z0, z1);
    float h0 = tanha(z0), h1 = tanha(z1);
    ull h2 = pk2(h0, h1);
    ull pt2 = fma2(h2, HALF2, HALF2);
    float q0, q1; upk2(pt2, q0, q1);
    float l0 = lg2a(q0), l1 = lg2a(q1);
    ull l2 = pk2(l0, l1);
    ull omp2 = fma2(h2, MHALF2, HALF2);
    ull o2   = mul2(omp2, omp2);
    ull g2   = mul2(l2, o2);
    ull a2   = fma2(t2, MHALF2, K75);
    A.f    = fma2(a2, g2, A.f);
    A.lg   = add2(A.lg, l2);
    A.omp  = add2(A.omp, omp2);
    A.tomp = fma2(t2, omp2, A.tomp);
    A.t    = add2(A.t, t2);
    ull bin2 = pk2(setgt0(x0), setgt0(x1));
    A.bin  = add2(A.bin, bin2);
    A.bint = fma2(t2, bin2, A.bint);
}

__device__ __forceinline__ float warp_sum(float v) {
    #pragma unroll
    for (int off = 16; off > 0; off >>= 1)
        v += __shfl_xor_sync(0xFFFFFFFFu, v, off);
    return v;
}

__global__ __launch_bounds__(NT, 4)
void loss_fused_kernel(const float4* __restrict__ pred,
                       const float4* __restrict__ gt,
                       const float*  __restrict__ pred_iou,
                       float*        __restrict__ out) {
    // Per-thread private staging: [slot][tid] 16B each -> 32 KB static smem
    __shared__ float4 st_p[NSLOT][NT];
    __shared__ float4 st_g[NSLOT][NT];

    const int tid = threadIdx.x;
    const int img = blockIdx.y;
    const int cta = blockIdx.x;

    // blocked-sequential partition: CTA owns contiguous [cta*CHUNK, ...)
    const float4* pbase = pred + (size_t)img * HW4 + (size_t)cta * CHUNK + tid;
    const float4* gbase = gt   + (size_t)img * HW4 + (size_t)cta * CHUNK + tid;

    const int nst = (cta < GRIDX - 1) ? 28 : 16;    // stages this CTA owns

    const uint32_t spb = smem_u32(&st_p[0][tid]);   // + slot*(NT*16)
    const uint32_t sgb = smem_u32(&st_g[0][tid]);

    // prologue: stage slots 0..2 (nst >= 16 > 3 always)
    #pragma unroll
    for (int j = 0; j < NSLOT - 1; j++) {
        cp16(spb + (uint32_t)j * (NT * 16), pbase + j * NT);
        cp16(sgb + (uint32_t)j * (NT * 16), gbase + j * NT);
        cp_commit();
    }

    const ull HALF2  = pk2(0.5f, 0.5f);
    const ull MHALF2 = pk2(-0.5f, -0.5f);
    const ull K75    = pk2(0.75f, 0.75f);

    Accs A;
    A.f = A.lg = A.omp = A.tomp = A.t = A.bin = A.bint = pk2(0.0f, 0.0f);

    for (int j = 0; j < nst; j++) {
        cp_wait2();                         // stage j's group complete
        const int slot = j & (NSLOT - 1);
        float4 p4 = st_p[slot][tid];
        float4 g4 = st_g[slot][tid];

        const int jn = j + NSLOT - 1;       // prefetch stage j+3 (adjacent 4KB)
        if (jn < nst) {
            const uint32_t soff = (uint32_t)(jn & (NSLOT - 1)) * (NT * 16);
            cp16(spb + soff, pbase + jn * NT);
            cp16(sgb + soff, gbase + jn * NT);
        }
        cp_commit();

        group(A, p4.x, p4.y, g4.x, g4.y, HALF2, MHALF2, K75);
        group(A, p4.z, p4.w, g4.z, g4.w, HALF2, MHALF2, K75);
    }

    // collapse packed halves
    float vals[NQ];
    {
        float lo, hi;
        upk2(A.f,    lo, hi); vals[0] = lo + hi;
        upk2(A.lg,   lo, hi); vals[1] = lo + hi;
        upk2(A.omp,  lo, hi); vals[2] = lo + hi;
        upk2(A.tomp, lo, hi); vals[3] = lo + hi;
        upk2(A.t,    lo, hi); vals[4] = lo + hi;
        upk2(A.bin,  lo, hi); vals[5] = lo + hi;
        upk2(A.bint, lo, hi); vals[6] = lo + hi;
    }

    // -------- block reduction --------
    #pragma unroll
    for (int q = 0; q < NQ; q++) vals[q] = warp_sum(vals[q]);

    __shared__ float sm[NT / 32][NQ];
    const int lane = tid & 31;
    const int warp = tid >> 5;
    if (lane == 0) {
        #pragma unroll
        for (int q = 0; q < NQ; q++) sm[warp][q] = vals[q];
    }
    __syncthreads();

    __shared__ bool is_last;
    if (warp == 0) {
        #pragma unroll
        for (int q = 0; q < NQ; q++) {
            float v = (lane < NT / 32) ? sm[lane][q] : 0.0f;
            v = warp_sum(v);
            if (lane == 0) vals[q] = v;
        }
        if (lane == 0) {
            float* dst = g_part + ((size_t)img * GRIDX + cta) * 8;
            #pragma unroll
            for (int q = 0; q < NQ; q++) dst[q] = vals[q];
            __threadfence();
            unsigned int v = atomicAdd(&g_count, 1u);
            is_last = (v == (unsigned int)(NBLOCKS - 1));
        }
    }
    __syncthreads();
    if (!is_last) return;

    // -------- epilogue: last block reduces 592 partials --------
    __shared__ float agg[BATCH][4];
    for (int b = warp; b < BATCH; b += NT / 32) {
        float s[NQ] = {0.f, 0.f, 0.f, 0.f, 0.f, 0.f, 0.f};
        for (int j = lane; j < GRIDX; j += 32) {
            const float* q = g_part + ((size_t)b * GRIDX + j) * 8;
            #pragma unroll
            for (int k = 0; k < NQ; k++) s[k] += q[k];
        }
        #pragma unroll
        for (int k = 0; k < NQ; k++) s[k] = warp_sum(s[k]);
        if (lane == 0) {
            // s: 0=f 1=lg 2=omp 3=tomp 4=t 5=bin 6=bint
            float Sp  = s[2] + s[4] - 2.0f * s[3];   // sum p
            float Spt = s[4] - s[3];                 // sum p*t
            float dice_term = (2.0f * Spt + SMOOTH) / (Sp + s[4] + SMOOTH);
            float inter  = s[6];
            float uni    = s[5] + s[4] - s[6];
            float actual = (inter + SMOOTH) / (uni + SMOOTH);
            float d = pred_iou[b] - actual;
            agg[b][0] = s[0];          // x (-ln2) later
            agg[b][1] = s[1];          // x (-ln2) later -> sum ce
            agg[b][2] = dice_term;
            agg[b][3] = d * d;
        }
    }
    __syncthreads();

    if (tid == 0) {
        float fsum = 0.f, csum = 0.f, dsum = 0.f, isum = 0.f;
        #pragma unroll
        for (int b = 0; b < BATCH; b++) {
            fsum += agg[b][0];
            csum += agg[b][1];
            dsum += agg[b][2];
            isum += agg[b][3];
        }
        const float NLN2 = -0.6931471805599453f;
        const float invN = 1.0f / (float)((long long)BATCH * HW);
        float focal    = NLN2 * fsum * invN;
        float dice     = 1.0f - dsum / (float)BATCH;
        float boundary = NLN2 * csum * invN;   // mean(ce) = 0.5*(2*mean(ce))
        float iou_loss = 0.1f * (isum / (float)BATCH);
        out[0] = focal + dice + boundary + iou_loss;
        g_count = 0;   // reset for next graph replay
    }
}

extern "C" void kernel_launch(void* const* d_in, const int* in_sizes, int n_in,
                              void* d_out, int out_size) {
    const float4* pred = (const float4*)d_in[0];
    const float4* gt   = (const float4*)d_in[1];
    const float*  piou = (const float*)d_in[2];
    float* out = (float*)d_out;

    dim3 grid(GRIDX, BATCH);
    loss_fused_kernel<<<grid, NT>>>(pred, gt, piou, out);
}